// round 2
// baseline (speedup 1.0000x reference)
#include <cuda_runtime.h>
#include <cstdint>

// Problem constants (fixed by setup_inputs)
#define BB 8
#define CC 256
#define HH 128
#define WW 96
#define HW (HH*WW)

// -------- scratch (device globals; no allocation allowed) --------
__device__ float g_corr[BB*49*HH*WW];   // lrelu(correlation)
__device__ float g_h1[BB*128*HH*WW];
__device__ float g_h2[BB*64*HH*WW];
__device__ float g_h3[BB*32*HH*WW];
__device__ float g_flow[BB*2*HH*WW];

__device__ __forceinline__ float lrelu_f(float v) { return v > 0.f ? v : 0.1f * v; }

// ============================================================================
// Correlation: out[b, dy*7+dx, h, w] = lrelu( (1/C) * sum_c f1[b,c,h,w] *
//                                      f2[b,c,h+dy-3,w+dx-3] )  (zero pad)
// Block = 96 threads (one row), grid = (H, B). 49 accumulators per thread.
// ============================================================================
#define CKC 8
__global__ __launch_bounds__(96) void corr_kernel(
    const float* __restrict__ f1, const float* __restrict__ f2,
    float* __restrict__ out)
{
    const int w = threadIdx.x;   // 0..95
    const int h = blockIdx.x;
    const int b = blockIdx.y;

    __shared__ float s2[CKC][7][104];   // rows h-3..h+3, cols (w-3)+3 => idx w+dx

    float acc[49];
#pragma unroll
    for (int i = 0; i < 49; ++i) acc[i] = 0.f;

    const float* f1p = f1 + ((size_t)b*CC*HH + h)*WW + w;

    for (int c0 = 0; c0 < CC; c0 += CKC) {
        __syncthreads();
        // load CKC channels of the 7-row window (cols -3..98 -> idx 0..101)
        for (int idx = w; idx < CKC*7*102; idx += 96) {
            int ci  = idx / 714;
            int rem = idx - ci*714;
            int r   = rem / 102;
            int col = rem - r*102;
            int gh = h + r - 3;
            int gw = col - 3;
            float v = 0.f;
            if ((unsigned)gh < (unsigned)HH && (unsigned)gw < (unsigned)WW)
                v = f2[(((size_t)b*CC + c0 + ci)*HH + gh)*WW + gw];
            s2[ci][r][col] = v;
        }
        __syncthreads();
#pragma unroll
        for (int ci = 0; ci < CKC; ++ci) {
            float a = f1p[(size_t)(c0 + ci)*HW];
#pragma unroll
            for (int dy = 0; dy < 7; ++dy) {
#pragma unroll
                for (int dx = 0; dx < 7; ++dx)
                    acc[dy*7 + dx] += a * s2[ci][dy][w + dx];
            }
        }
    }

#pragma unroll
    for (int o = 0; o < 49; ++o) {
        float t = acc[o] * (1.0f/256.0f);
        out[(((size_t)b*49 + o)*HH + h)*WW + w] = lrelu_f(t);
    }
}

// ============================================================================
// 3x3 conv, pad 1, NCHW/OIHW. Register-tiled:
//   block = 128 thr; tile = 16 couts x 4h x 32w.
//   warp = one group of 4 couts; lane -> (sh in 0..3, sw = 4*(lane&7)).
//   thread computes 4 couts x 4 pixels (16 accumulators).
// Per cin: 18 scalar input LDS (conflict-free, stride 37) + 9 broadcast
// float4 weight LDS + 144 FMA.
// ============================================================================
template<int CIN, int COUT, bool RELU>
__global__ __launch_bounds__(128) void conv3x3_kernel(
    const float* __restrict__ x, const float* __restrict__ wgt,
    const float* __restrict__ bias, float* __restrict__ y)
{
    constexpr int CK = 16;
    const int tid  = threadIdx.x;
    const int w0   = blockIdx.x * 32;
    const int h0   = blockIdx.y * 4;
    constexpr int NZC = COUT / 16;
    const int co0  = (blockIdx.z % NZC) * 16;
    const int b    = blockIdx.z / NZC;

    const int grp  = tid >> 5;            // 0..3 (cout group of 4)
    const int lane = tid & 31;
    const int sh   = lane >> 3;           // 0..3
    const int sw   = (lane & 7) * 4;      // 0,4,...,28

    __shared__ float s_in[CK][6][37];     // rows h0-1..h0+4, cols w0-1..w0+32
    __shared__ float s_w[CK][4][9][4];    // [cin][grp][tap][co-in-grp]

    float acc[4][4];
#pragma unroll
    for (int i = 0; i < 4; ++i)
#pragma unroll
        for (int j = 0; j < 4; ++j) acc[i][j] = 0.f;

    for (int c0 = 0; c0 < CIN; c0 += CK) {
        const int ckn = (CIN - c0) < CK ? (CIN - c0) : CK;
        __syncthreads();
        // ---- load input tile ----
        for (int idx = tid; idx < ckn*6*34; idx += 128) {
            int ci  = idx / 204;
            int rem = idx - ci*204;
            int r   = rem / 34;
            int col = rem - r*34;
            int gh = h0 + r - 1;
            int gw = w0 + col - 1;
            float v = 0.f;
            if ((unsigned)gh < (unsigned)HH && (unsigned)gw < (unsigned)WW)
                v = x[(((size_t)b*CIN + c0 + ci)*HH + gh)*WW + gw];
            s_in[ci][r][col] = v;
        }
        // ---- load weights ----
        for (int idx = tid; idx < ckn*16*9; idx += 128) {
            int ci  = idx / 144;
            int rem = idx - ci*144;
            int co  = rem / 9;
            int k   = rem - co*9;
            s_w[ci][co >> 2][k][co & 3] =
                wgt[((size_t)(co0 + co)*CIN + c0 + ci)*9 + k];
        }
        __syncthreads();

        for (int ci = 0; ci < ckn; ++ci) {
            float in_r[3][6];
#pragma unroll
            for (int r = 0; r < 3; ++r)
#pragma unroll
                for (int cc = 0; cc < 6; ++cc)
                    in_r[r][cc] = s_in[ci][sh + r][sw + cc];
#pragma unroll
            for (int ky = 0; ky < 3; ++ky) {
#pragma unroll
                for (int kx = 0; kx < 3; ++kx) {
                    float4 wv = *reinterpret_cast<const float4*>(&s_w[ci][grp][ky*3 + kx][0]);
#pragma unroll
                    for (int px = 0; px < 4; ++px) {
                        float iv = in_r[ky][kx + px];
                        acc[0][px] += wv.x * iv;
                        acc[1][px] += wv.y * iv;
                        acc[2][px] += wv.z * iv;
                        acc[3][px] += wv.w * iv;
                    }
                }
            }
        }
    }

    // ---- epilogue ----
#pragma unroll
    for (int co = 0; co < 4; ++co) {
        int coG = co0 + grp*4 + co;
        float bv = bias[coG];
#pragma unroll
        for (int px = 0; px < 4; ++px) {
            float v = acc[co][px] + bv;
            if (RELU) v = lrelu_f(v);
            y[(((size_t)b*COUT + coG)*HH + h0 + sh)*WW + w0 + sw + px] = v;
        }
    }
}

// ============================================================================
// Final 3x3 conv 32 -> 2 (flow). Small; thread per pixel, weights in smem.
// ============================================================================
__global__ __launch_bounds__(256) void conv_last_kernel(
    const float* __restrict__ x, const float* __restrict__ wgt,
    const float* __restrict__ bias, float* __restrict__ flow)
{
    __shared__ float sw[2*32*9];
    for (int i = threadIdx.x; i < 2*32*9; i += 256) sw[i] = wgt[i];
    __syncthreads();

    int idx = blockIdx.x*256 + threadIdx.x;    // grid sized exactly
    int w = idx % WW;
    int h = (idx / WW) % HH;
    int b = idx / (WW*HH);

    float a0 = bias[0], a1 = bias[1];
    for (int ci = 0; ci < 32; ++ci) {
        const float* xp = x + ((size_t)(b*32 + ci))*HW;
        const float* w0p = &sw[(0*32 + ci)*9];
        const float* w1p = &sw[(1*32 + ci)*9];
#pragma unroll
        for (int ky = 0; ky < 3; ++ky) {
            int gh = h + ky - 1;
            if ((unsigned)gh >= (unsigned)HH) continue;
#pragma unroll
            for (int kx = 0; kx < 3; ++kx) {
                int gw = w + kx - 1;
                if ((unsigned)gw >= (unsigned)WW) continue;
                float v = xp[gh*WW + gw];
                a0 += v * w0p[ky*3 + kx];
                a1 += v * w1p[ky*3 + kx];
            }
        }
    }
    flow[((size_t)b*2*HH + h)*WW + w]        = a0;
    flow[(((size_t)b*2 + 1)*HH + h)*WW + w]  = a1;
}

// ============================================================================
// apply_offset + grid_sample fused:
//   x = clamp(w + fx, 0, W-1), y = clamp(h + fy, 0, H-1), bilinear w/ clamp.
// One thread per output element (b,c,h,w); flow reads hit L1/L2.
// ============================================================================
__global__ __launch_bounds__(256) void warp_kernel(
    const float* __restrict__ f2, const float* __restrict__ flow,
    float* __restrict__ out)
{
    int idx = blockIdx.x*256 + threadIdx.x;   // grid sized exactly to B*C*H*W
    int w = idx % WW;
    int h = (idx / WW) % HH;
    int c = (idx / HW) % CC;
    int b = idx / (HW*CC);

    float fx = flow[((size_t)b*2*HH + h)*WW + w];
    float fy = flow[(((size_t)b*2 + 1)*HH + h)*WW + w];

    float xx = fminf(fmaxf((float)w + fx, 0.f), (float)(WW-1));
    float yy = fminf(fmaxf((float)h + fy, 0.f), (float)(HH-1));
    float x0f = floorf(xx), y0f = floorf(yy);
    float wx = xx - x0f,  wy = yy - y0f;
    int x0 = (int)x0f, y0 = (int)y0f;
    int x1 = min(x0 + 1, WW-1);
    int y1 = min(y0 + 1, HH-1);

    const float* p = f2 + ((size_t)(b*CC + c))*HW;
    float v00 = p[y0*WW + x0];
    float v01 = p[y0*WW + x1];
    float v10 = p[y1*WW + x0];
    float v11 = p[y1*WW + x1];

    out[idx] = v00*(1.f-wx)*(1.f-wy) + v01*wx*(1.f-wy)
             + v10*(1.f-wx)*wy       + v11*wx*wy;
}

// ============================================================================
// launch
// ============================================================================
extern "C" void kernel_launch(void* const* d_in, const int* in_sizes, int n_in,
                              void* d_out, int out_size)
{
    const float* feat1 = (const float*)d_in[0];
    const float* feat2 = (const float*)d_in[1];
    const float* w1 = (const float*)d_in[2];
    const float* b1 = (const float*)d_in[3];
    const float* w2 = (const float*)d_in[4];
    const float* b2 = (const float*)d_in[5];
    const float* w3 = (const float*)d_in[6];
    const float* b3 = (const float*)d_in[7];
    const float* w4 = (const float*)d_in[8];
    const float* b4 = (const float*)d_in[9];
    float* out = (float*)d_out;

    float *p_corr, *p_h1, *p_h2, *p_h3, *p_flow;
    cudaGetSymbolAddress((void**)&p_corr, g_corr);
    cudaGetSymbolAddress((void**)&p_h1,   g_h1);
    cudaGetSymbolAddress((void**)&p_h2,   g_h2);
    cudaGetSymbolAddress((void**)&p_h3,   g_h3);
    cudaGetSymbolAddress((void**)&p_flow, g_flow);

    corr_kernel<<<dim3(HH, BB), 96>>>(feat1, feat2, p_corr);

    conv3x3_kernel<49, 128, true><<<dim3(3, 32, BB*8), 128>>>(p_corr, w1, b1, p_h1);
    conv3x3_kernel<128, 64, true><<<dim3(3, 32, BB*4), 128>>>(p_h1,  w2, b2, p_h2);
    conv3x3_kernel<64,  32, true><<<dim3(3, 32, BB*2), 128>>>(p_h2,  w3, b3, p_h3);

    conv_last_kernel<<<(BB*HH*WW)/256, 256>>>(p_h3, w4, b4, p_flow);

    warp_kernel<<<(BB*CC*HH*WW)/256, 256>>>(feat2, p_flow, out);
}

// round 4
// speedup vs baseline: 1.3242x; 1.3242x over previous
#include <cuda_runtime.h>
#include <cstdint>

// Problem constants (fixed by setup_inputs)
#define BB 8
#define CC 256
#define HH 128
#define WW 96
#define HW (HH*WW)

// -------- scratch (device globals; no allocation allowed) --------
__device__ float g_corr[BB*49*HH*WW];   // lrelu(correlation)
__device__ float g_h1[BB*128*HH*WW];
__device__ float g_h2[BB*64*HH*WW];
__device__ float g_h3[BB*32*HH*WW];
__device__ float g_flow[BB*2*HH*WW];

__device__ __forceinline__ float lrelu_f(float v) { return v > 0.f ? v : 0.1f * v; }

__device__ __forceinline__ uint32_t f2tf32(float v) {
    uint32_t r;
    asm("cvt.rna.tf32.f32 %0, %1;" : "=r"(r) : "f"(v));
    return r;
}

// mma.sync m16n8k8 tf32, fp32 accumulate
__device__ __forceinline__ void mma_tf32(float* d, const uint32_t* a, const uint32_t* b) {
    asm volatile(
        "mma.sync.aligned.m16n8k8.row.col.f32.tf32.tf32.f32 "
        "{%0,%1,%2,%3}, {%4,%5,%6,%7}, {%8,%9}, {%0,%1,%2,%3};"
        : "+f"(d[0]), "+f"(d[1]), "+f"(d[2]), "+f"(d[3])
        : "r"(a[0]), "r"(a[1]), "r"(a[2]), "r"(a[3]),
          "r"(b[0]), "r"(b[1]));
}

// ============================================================================
// Correlation (unchanged from R1 — known correct; ~LDS-BW bound)
// ============================================================================
#define CKC 8
__global__ __launch_bounds__(96) void corr_kernel(
    const float* __restrict__ f1, const float* __restrict__ f2,
    float* __restrict__ out)
{
    const int w = threadIdx.x;   // 0..95
    const int h = blockIdx.x;
    const int b = blockIdx.y;

    __shared__ float s2[CKC][7][104];

    float acc[49];
#pragma unroll
    for (int i = 0; i < 49; ++i) acc[i] = 0.f;

    const float* f1p = f1 + ((size_t)b*CC*HH + h)*WW + w;

    for (int c0 = 0; c0 < CC; c0 += CKC) {
        __syncthreads();
        for (int idx = w; idx < CKC*7*102; idx += 96) {
            int ci  = idx / 714;
            int rem = idx - ci*714;
            int r   = rem / 102;
            int col = rem - r*102;
            int gh = h + r - 3;
            int gw = col - 3;
            float v = 0.f;
            if ((unsigned)gh < (unsigned)HH && (unsigned)gw < (unsigned)WW)
                v = f2[(((size_t)b*CC + c0 + ci)*HH + gh)*WW + gw];
            s2[ci][r][col] = v;
        }
        __syncthreads();
#pragma unroll
        for (int ci = 0; ci < CKC; ++ci) {
            float a = f1p[(size_t)(c0 + ci)*HW];
#pragma unroll
            for (int dy = 0; dy < 7; ++dy) {
#pragma unroll
                for (int dx = 0; dx < 7; ++dx)
                    acc[dy*7 + dx] += a * s2[ci][dy][w + dx];
            }
        }
    }

#pragma unroll
    for (int o = 0; o < 49; ++o) {
        float t = acc[o] * (1.0f/256.0f);
        out[(((size_t)b*49 + o)*HH + h)*WW + w] = lrelu_f(t);
    }
}

// ============================================================================
// 3x3 conv, pad 1, NCHW/OIHW — tensor-core implicit GEMM (tf32 mma.sync).
//
// Block = 128 thr (4 warps). Output tile: 32 couts x 4h x 32w.
// Warp w handles row h0+w, all 32 couts (2 m16 tiles), 32 pixels (4 n8 tiles).
// K loop: 9 taps x ci-chunks of 16 (2 k8 sub-chunks).
//
// smem s_in: [ci][row 6][col 36], ci-stride 216 floats (216 % 32 == 8 ->
//   B-frag LDS banks = 8*(lane%4) + lane/4, conflict-free).
// smem s_w : [ci][tap][co 36], ci-stride 328 floats (328 % 32 == 8 ->
//   A-frag LDS conflict-free).
// ============================================================================
template<int CIN, int COUT, bool RELU>
__global__ __launch_bounds__(128) void conv3x3_mma(
    const float* __restrict__ x, const float* __restrict__ wgt,
    const float* __restrict__ bias, float* __restrict__ y)
{
    constexpr int CK  = 16;
    constexpr int R   = 36;            // row stride (floats); cols 0..33 used
    constexpr int S   = 6 * R;         // 216: ci stride in s_in
    constexpr int WS  = 36;            // co stride in s_w
    constexpr int CIS = 9 * WS + 4;    // 328: ci stride in s_w

    __shared__ float s_in[CK * S];     // 13824 B
    __shared__ float s_w [CK * CIS];   // 20992 B

    const int tid  = threadIdx.x;
    const int warp = tid >> 5;
    const int lane = tid & 31;

    const int w0 = blockIdx.x * 32;
    const int h0 = blockIdx.y * 4;
    constexpr int NCO = COUT / 32;
    const int co0 = (blockIdx.z % NCO) * 32;
    const int b   = blockIdx.z / NCO;

    float d[2][4][4];
#pragma unroll
    for (int m = 0; m < 2; ++m)
#pragma unroll
        for (int n = 0; n < 4; ++n)
#pragma unroll
            for (int k = 0; k < 4; ++k) d[m][n][k] = 0.f;

    // weight-loader roles: thread -> co = tid>>2, ci base = (tid&3)*4
    const int l_co  = tid >> 2;         // 0..31
    const int l_cis = (tid & 3) * 4;    // 0,4,8,12

    for (int c0 = 0; c0 < CIN; c0 += CK) {
        __syncthreads();
        // ---- input tile: CK x 6 x 34 (rows h0-1..h0+4, cols w0-1..w0+32) ----
        for (int idx = tid; idx < CK*6*34; idx += 128) {
            int ci  = idx / 204;
            int rem = idx - ci*204;
            int r   = rem / 34;
            int col = rem - r*34;
            int gh = h0 + r - 1;
            int gw = w0 + col - 1;
            float v = 0.f;
            if (c0 + ci < CIN && (unsigned)gh < (unsigned)HH && (unsigned)gw < (unsigned)WW)
                v = x[(((size_t)b*CIN + c0 + ci)*HH + gh)*WW + gw];
            s_in[ci*S + r*R + col] = __uint_as_float(f2tf32(v));
        }
        // ---- weights: each thread loads 4 ci x 9 taps for its co (contig 36 floats) ----
#pragma unroll
        for (int cil = 0; cil < 4; ++cil) {
            int ci = l_cis + cil;
            bool ok = (c0 + ci) < CIN;
            const float* wp = wgt + ((size_t)(co0 + l_co)*CIN + c0 + ci)*9;
#pragma unroll
            for (int tap = 0; tap < 9; ++tap) {
                float v = ok ? wp[tap] : 0.f;
                s_w[ci*CIS + tap*WS + l_co] = __uint_as_float(f2tf32(v));
            }
        }
        __syncthreads();

        const uint32_t* si  = (const uint32_t*)s_in;
        const uint32_t* swp = (const uint32_t*)s_w;

#pragma unroll
        for (int ky = 0; ky < 3; ++ky) {
#pragma unroll
            for (int kx = 0; kx < 3; ++kx) {
                const int tap = ky*3 + kx;
#pragma unroll
                for (int kc = 0; kc < 2; ++kc) {
                    // ---- A fragments (weights): A[co][ci] ----
                    // a0:(co,ci) a1:(co+8,ci) a2:(co,ci+4) a3:(co+8,ci+4)
                    const int ciA = kc*8 + (lane & 3);
                    const int coA = lane >> 2;
                    uint32_t a[2][4];
#pragma unroll
                    for (int m = 0; m < 2; ++m) {
                        int cob = m*16 + coA;
                        a[m][0] = swp[ ciA   *CIS + tap*WS + cob    ];
                        a[m][1] = swp[ ciA   *CIS + tap*WS + cob + 8];
                        a[m][2] = swp[(ciA+4)*CIS + tap*WS + cob    ];
                        a[m][3] = swp[(ciA+4)*CIS + tap*WS + cob + 8];
                    }
                    // ---- B fragments (input): B[ci][px] ----
                    // b0:(ci, n) b1:(ci+4, n); ci=kc*8+lane%4, n=lane>>2
                    const int rB  = warp + ky;
                    const int ciB = kc*8 + (lane & 3);
                    const int nB  = lane >> 2;
                    const uint32_t* bbase = si + ciB*S + rB*R + nB + kx;
#pragma unroll
                    for (int nt = 0; nt < 4; ++nt) {
                        uint32_t bf[2];
                        bf[0] = bbase[nt*8];
                        bf[1] = bbase[nt*8 + 4*S];
                        mma_tf32(d[0][nt], a[0], bf);
                        mma_tf32(d[1][nt], a[1], bf);
                    }
                }
            }
        }
    }

    // ---- epilogue ----
    // c0:(row=lane>>2, col=(lane&3)*2) c1:col+1 c2:row+8 c3:row+8,col+1
#pragma unroll
    for (int m = 0; m < 2; ++m) {
        int co  = co0 + m*16 + (lane >> 2);
        float bv0 = bias[co];
        float bv1 = bias[co + 8];
        int h = h0 + warp;
#pragma unroll
        for (int nt = 0; nt < 4; ++nt) {
            int wc = w0 + nt*8 + (lane & 3)*2;
            float v0 = d[m][nt][0] + bv0;
            float v1 = d[m][nt][1] + bv0;
            float v2 = d[m][nt][2] + bv1;
            float v3 = d[m][nt][3] + bv1;
            if (RELU) {
                v0 = lrelu_f(v0); v1 = lrelu_f(v1);
                v2 = lrelu_f(v2); v3 = lrelu_f(v3);
            }
            float* yp = y + (((size_t)b*COUT + co)*HH + h)*WW + wc;
            yp[0]        = v0;
            yp[1]        = v1;
            yp[8*HW]     = v2;
            yp[8*HW + 1] = v3;
        }
    }
}

// ============================================================================
// Final 3x3 conv 32 -> 2 (flow). Unchanged.
// ============================================================================
__global__ __launch_bounds__(256) void conv_last_kernel(
    const float* __restrict__ x, const float* __restrict__ wgt,
    const float* __restrict__ bias, float* __restrict__ flow)
{
    __shared__ float sw[2*32*9];
    for (int i = threadIdx.x; i < 2*32*9; i += 256) sw[i] = wgt[i];
    __syncthreads();

    int idx = blockIdx.x*256 + threadIdx.x;
    int w = idx % WW;
    int h = (idx / WW) % HH;
    int b = idx / (WW*HH);

    float a0 = bias[0], a1 = bias[1];
    for (int ci = 0; ci < 32; ++ci) {
        const float* xp = x + ((size_t)(b*32 + ci))*HW;
        const float* w0p = &sw[(0*32 + ci)*9];
        const float* w1p = &sw[(1*32 + ci)*9];
#pragma unroll
        for (int ky = 0; ky < 3; ++ky) {
            int gh = h + ky - 1;
            if ((unsigned)gh >= (unsigned)HH) continue;
#pragma unroll
            for (int kx = 0; kx < 3; ++kx) {
                int gw = w + kx - 1;
                if ((unsigned)gw >= (unsigned)WW) continue;
                float v = xp[gh*WW + gw];
                a0 += v * w0p[ky*3 + kx];
                a1 += v * w1p[ky*3 + kx];
            }
        }
    }
    flow[((size_t)b*2*HH + h)*WW + w]        = a0;
    flow[(((size_t)b*2 + 1)*HH + h)*WW + w]  = a1;
}

// ============================================================================
// apply_offset + grid_sample fused. Unchanged.
// ============================================================================
__global__ __launch_bounds__(256) void warp_kernel(
    const float* __restrict__ f2, const float* __restrict__ flow,
    float* __restrict__ out)
{
    int idx = blockIdx.x*256 + threadIdx.x;
    int w = idx % WW;
    int h = (idx / WW) % HH;
    int c = (idx / HW) % CC;
    int b = idx / (HW*CC);

    float fx = flow[((size_t)b*2*HH + h)*WW + w];
    float fy = flow[(((size_t)b*2 + 1)*HH + h)*WW + w];

    float xx = fminf(fmaxf((float)w + fx, 0.f), (float)(WW-1));
    float yy = fminf(fmaxf((float)h + fy, 0.f), (float)(HH-1));
    float x0f = floorf(xx), y0f = floorf(yy);
    float wx = xx - x0f,  wy = yy - y0f;
    int x0 = (int)x0f, y0 = (int)y0f;
    int x1 = min(x0 + 1, WW-1);
    int y1 = min(y0 + 1, HH-1);

    const float* p = f2 + ((size_t)(b*CC + c))*HW;
    float v00 = p[y0*WW + x0];
    float v01 = p[y0*WW + x1];
    float v10 = p[y1*WW + x0];
    float v11 = p[y1*WW + x1];

    out[idx] = v00*(1.f-wx)*(1.f-wy) + v01*wx*(1.f-wy)
             + v10*(1.f-wx)*wy       + v11*wx*wy;
}

// ============================================================================
// launch
// ============================================================================
extern "C" void kernel_launch(void* const* d_in, const int* in_sizes, int n_in,
                              void* d_out, int out_size)
{
    const float* feat1 = (const float*)d_in[0];
    const float* feat2 = (const float*)d_in[1];
    const float* w1 = (const float*)d_in[2];
    const float* b1 = (const float*)d_in[3];
    const float* w2 = (const float*)d_in[4];
    const float* b2 = (const float*)d_in[5];
    const float* w3 = (const float*)d_in[6];
    const float* b3 = (const float*)d_in[7];
    const float* w4 = (const float*)d_in[8];
    const float* b4 = (const float*)d_in[9];
    float* out = (float*)d_out;

    float *p_corr, *p_h1, *p_h2, *p_h3, *p_flow;
    cudaGetSymbolAddress((void**)&p_corr, g_corr);
    cudaGetSymbolAddress((void**)&p_h1,   g_h1);
    cudaGetSymbolAddress((void**)&p_h2,   g_h2);
    cudaGetSymbolAddress((void**)&p_h3,   g_h3);
    cudaGetSymbolAddress((void**)&p_flow, g_flow);

    corr_kernel<<<dim3(HH, BB), 96>>>(feat1, feat2, p_corr);

    // tensor-core convs: grid = (w-tiles, h-tiles, B * cout-tiles)
    conv3x3_mma<49, 128, true><<<dim3(3, 32, BB*4), 128>>>(p_corr, w1, b1, p_h1);
    conv3x3_mma<128, 64, true><<<dim3(3, 32, BB*2), 128>>>(p_h1,  w2, b2, p_h2);
    conv3x3_mma<64,  32, true><<<dim3(3, 32, BB*1), 128>>>(p_h2,  w3, b3, p_h3);

    conv_last_kernel<<<(BB*HH*WW)/256, 256>>>(p_h3, w4, b4, p_flow);

    warp_kernel<<<(BB*CC*HH*WW)/256, 256>>>(feat2, p_flow, out);
}

// round 5
// speedup vs baseline: 2.0029x; 1.5125x over previous
#include <cuda_runtime.h>
#include <cstdint>

// Problem constants (fixed by setup_inputs)
#define BB 8
#define CC 256
#define HH 128
#define WW 96
#define HW (HH*WW)

// -------- scratch (device globals; no allocation allowed) --------
__device__ float g_corr[BB*49*HH*WW];   // lrelu(correlation)
__device__ float g_h1[BB*128*HH*WW];
__device__ float g_h2[BB*64*HH*WW];
__device__ float g_h3[BB*32*HH*WW];
__device__ float g_flow[BB*2*HH*WW];

__device__ __forceinline__ float lrelu_f(float v) { return v > 0.f ? v : 0.1f * v; }

// mma.sync m16n8k8 tf32, fp32 accumulate (raw f32 regs; HW uses tf32 bits)
__device__ __forceinline__ void mma_tf32(float* d, const uint32_t* a, const uint32_t* b) {
    asm volatile(
        "mma.sync.aligned.m16n8k8.row.col.f32.tf32.tf32.f32 "
        "{%0,%1,%2,%3}, {%4,%5,%6,%7}, {%8,%9}, {%0,%1,%2,%3};"
        : "+f"(d[0]), "+f"(d[1]), "+f"(d[2]), "+f"(d[3])
        : "r"(a[0]), "r"(a[1]), "r"(a[2]), "r"(a[3]),
          "r"(b[0]), "r"(b[1]));
}

// -------- cp.async helpers --------
__device__ __forceinline__ void cp_async4(uint32_t dst, const float* src, bool v) {
    asm volatile("cp.async.ca.shared.global [%0], [%1], 4, %2;"
                 :: "r"(dst), "l"(src), "r"(v ? 4u : 0u));
}
__device__ __forceinline__ void cp_commit() {
    asm volatile("cp.async.commit_group;");
}
template<int N> __device__ __forceinline__ void cp_wait() {
    asm volatile("cp.async.wait_group %0;" :: "n"(N));
}

// ============================================================================
// Correlation: out[b, dy*7+dx, h, w] = lrelu((1/C) * sum_c f1[b,c,h,w] *
//              f2[b,c,h+dy-3,w+dx-3])  (zero pad)
// Block = 384 thr = 4 output rows x 96 cols. Shared window = 10 rows.
// 4x traffic reduction vs 1-row blocks; 12 warps/block.
// ============================================================================
#define CKC 8
__global__ __launch_bounds__(384) void corr_kernel(
    const float* __restrict__ f1, const float* __restrict__ f2,
    float* __restrict__ out)
{
    const int tid = threadIdx.x;
    const int w   = tid % 96;
    const int r   = tid / 96;           // 0..3
    const int h0  = blockIdx.x * 4;
    const int b   = blockIdx.y;
    const int h   = h0 + r;

    __shared__ float s2[CKC][10][104];  // rows h0-3 .. h0+6, cols -3..98

    float acc[49];
#pragma unroll
    for (int i = 0; i < 49; ++i) acc[i] = 0.f;

    const float* f1p = f1 + ((size_t)b*CC*HH + h)*WW + w;

    for (int c0 = 0; c0 < CC; c0 += CKC) {
        __syncthreads();
        for (int idx = tid; idx < CKC*10*102; idx += 384) {
            int ci  = idx / 1020;
            int rem = idx - ci*1020;
            int rr  = rem / 102;
            int col = rem - rr*102;
            int gh = h0 + rr - 3;
            int gw = col - 3;
            float v = 0.f;
            if ((unsigned)gh < (unsigned)HH && (unsigned)gw < (unsigned)WW)
                v = f2[(((size_t)b*CC + c0 + ci)*HH + gh)*WW + gw];
            s2[ci][rr][col] = v;
        }
        __syncthreads();
#pragma unroll
        for (int ci = 0; ci < CKC; ++ci) {
            float a = f1p[(size_t)(c0 + ci)*HW];
#pragma unroll
            for (int dy = 0; dy < 7; ++dy) {
#pragma unroll
                for (int dx = 0; dx < 7; ++dx)
                    acc[dy*7 + dx] += a * s2[ci][r + dy][w + dx];
            }
        }
    }

#pragma unroll
    for (int o = 0; o < 49; ++o) {
        float t = acc[o] * (1.0f/256.0f);
        out[(((size_t)b*49 + o)*HH + h)*WW + w] = lrelu_f(t);
    }
}

// ============================================================================
// 3x3 conv, pad 1, NCHW/OIHW — tf32 mma.sync implicit GEMM, cp.async
// double-buffered over ci-chunks of 8.
// Block = 128 thr (4 warps). Output tile: 32 couts x 4h x 32w.
// smem strides: S=216 (216%32==8), CIS=328 (328%32==8) -> conflict-free frags.
// ============================================================================
template<int CIN, int COUT, bool RELU>
__global__ __launch_bounds__(128) void conv3x3_mma(
    const float* __restrict__ x, const float* __restrict__ wgt,
    const float* __restrict__ bias, float* __restrict__ y)
{
    constexpr int CK  = 8;
    constexpr int R   = 36;            // row stride (floats)
    constexpr int S   = 6 * R;         // 216: ci stride in s_in
    constexpr int WS  = 36;            // tap stride in s_w
    constexpr int CIS = 9 * WS + 4;    // 328: ci stride in s_w
    constexpr int NCH = (CIN + CK - 1) / CK;

    __shared__ float s_in[2][CK * S];    // 2 x 6912 B
    __shared__ float s_w [2][CK * CIS];  // 2 x 10496 B

    const int tid  = threadIdx.x;
    const int warp = tid >> 5;
    const int lane = tid & 31;

    const int w0 = blockIdx.x * 32;
    const int h0 = blockIdx.y * 4;
    constexpr int NCO = COUT / 32;
    const int co0 = (blockIdx.z % NCO) * 32;
    const int b   = blockIdx.z / NCO;

    float d[2][4][4];
#pragma unroll
    for (int m = 0; m < 2; ++m)
#pragma unroll
        for (int n = 0; n < 4; ++n)
#pragma unroll
            for (int k = 0; k < 4; ++k) d[m][n][k] = 0.f;

    // weight loader role: thread -> co = tid>>2, sub-lane j = tid&3
    const int l_co = tid >> 2;
    const int l_j  = tid & 3;
    const float* wbase = wgt + (size_t)(co0 + l_co)*CIN*9;

    // ---- chunk issue (cp.async into buffer bf) ----
    auto issue = [&](int c0, int bf) {
        uint32_t sb_in = (uint32_t)__cvta_generic_to_shared(&s_in[bf][0]);
        uint32_t sb_w  = (uint32_t)__cvta_generic_to_shared(&s_w[bf][0]);
        // input tile: CK x 6 x 34 (rows h0-1..h0+4, cols w0-1..w0+32)
        for (int idx = tid; idx < CK*6*34; idx += 128) {
            int ci  = idx / 204;
            int rem = idx - ci*204;
            int rr  = rem / 34;
            int col = rem - rr*34;
            int gh = h0 + rr - 1;
            int gw = w0 + col - 1;
            bool v = (c0 + ci < CIN) &&
                     (unsigned)gh < (unsigned)HH && (unsigned)gw < (unsigned)WW;
            const float* src = v ?
                x + (((size_t)b*CIN + c0 + ci)*HH + gh)*WW + gw : x;
            cp_async4(sb_in + (uint32_t)(ci*S + rr*R + col)*4u, src, v);
        }
        // weights: per thread, its co, elems j, j+4, ... over ci*9+tap
        const float* wp = wbase + (size_t)c0*9;
#pragma unroll
        for (int e = l_j; e < CK*9; e += 4) {
            int ci  = e / 9;
            int tap = e - ci*9;
            bool v = (c0 + ci) < CIN;
            cp_async4(sb_w + (uint32_t)(ci*CIS + tap*WS + l_co)*4u,
                      v ? wp + e : wgt, v);
        }
    };

    issue(0, 0);
    cp_commit();

    int buf = 0;
    for (int ch = 0; ch < NCH; ++ch) {
        if (ch + 1 < NCH) {
            issue((ch + 1)*CK, buf ^ 1);
            cp_commit();
            cp_wait<1>();
        } else {
            cp_wait<0>();
        }
        __syncthreads();

        const uint32_t* si  = (const uint32_t*)&s_in[buf][0];
        const uint32_t* swp = (const uint32_t*)&s_w[buf][0];

#pragma unroll
        for (int ky = 0; ky < 3; ++ky) {
#pragma unroll
            for (int kx = 0; kx < 3; ++kx) {
                const int tap = ky*3 + kx;
                // ---- A fragments (weights) ----
                const int ciA = lane & 3;
                const int coA = lane >> 2;
                uint32_t a[2][4];
#pragma unroll
                for (int m = 0; m < 2; ++m) {
                    int cob = m*16 + coA;
                    a[m][0] = swp[ ciA   *CIS + tap*WS + cob    ];
                    a[m][1] = swp[ ciA   *CIS + tap*WS + cob + 8];
                    a[m][2] = swp[(ciA+4)*CIS + tap*WS + cob    ];
                    a[m][3] = swp[(ciA+4)*CIS + tap*WS + cob + 8];
                }
                // ---- B fragments (input) ----
                const int rB  = warp + ky;
                const int ciB = lane & 3;
                const int nB  = lane >> 2;
                const uint32_t* bbase = si + ciB*S + rB*R + nB + kx;
#pragma unroll
                for (int nt = 0; nt < 4; ++nt) {
                    uint32_t bf[2];
                    bf[0] = bbase[nt*8];
                    bf[1] = bbase[nt*8 + 4*S];
                    mma_tf32(d[0][nt], a[0], bf);
                    mma_tf32(d[1][nt], a[1], bf);
                }
            }
        }
        __syncthreads();
        buf ^= 1;
    }

    // ---- epilogue ----
#pragma unroll
    for (int m = 0; m < 2; ++m) {
        int co  = co0 + m*16 + (lane >> 2);
        float bv0 = bias[co];
        float bv1 = bias[co + 8];
        int h = h0 + warp;
#pragma unroll
        for (int nt = 0; nt < 4; ++nt) {
            int wc = w0 + nt*8 + (lane & 3)*2;
            float v0 = d[m][nt][0] + bv0;
            float v1 = d[m][nt][1] + bv0;
            float v2 = d[m][nt][2] + bv1;
            float v3 = d[m][nt][3] + bv1;
            if (RELU) {
                v0 = lrelu_f(v0); v1 = lrelu_f(v1);
                v2 = lrelu_f(v2); v3 = lrelu_f(v3);
            }
            float* yp = y + (((size_t)b*COUT + co)*HH + h)*WW + wc;
            yp[0]        = v0;
            yp[1]        = v1;
            yp[8*HW]     = v2;
            yp[8*HW + 1] = v3;
        }
    }
}

// ============================================================================
// Final 3x3 conv 32 -> 2 (flow).
// ============================================================================
__global__ __launch_bounds__(256) void conv_last_kernel(
    const float* __restrict__ x, const float* __restrict__ wgt,
    const float* __restrict__ bias, float* __restrict__ flow)
{
    __shared__ float sw[2*32*9];
    for (int i = threadIdx.x; i < 2*32*9; i += 256) sw[i] = wgt[i];
    __syncthreads();

    int idx = blockIdx.x*256 + threadIdx.x;
    int w = idx % WW;
    int h = (idx / WW) % HH;
    int b = idx / (WW*HH);

    float a0 = bias[0], a1 = bias[1];
    for (int ci = 0; ci < 32; ++ci) {
        const float* xp = x + ((size_t)(b*32 + ci))*HW;
        const float* w0p = &sw[(0*32 + ci)*9];
        const float* w1p = &sw[(1*32 + ci)*9];
#pragma unroll
        for (int ky = 0; ky < 3; ++ky) {
            int gh = h + ky - 1;
            if ((unsigned)gh >= (unsigned)HH) continue;
#pragma unroll
            for (int kx = 0; kx < 3; ++kx) {
                int gw = w + kx - 1;
                if ((unsigned)gw >= (unsigned)WW) continue;
                float v = xp[gh*WW + gw];
                a0 += v * w0p[ky*3 + kx];
                a1 += v * w1p[ky*3 + kx];
            }
        }
    }
    flow[((size_t)b*2*HH + h)*WW + w]        = a0;
    flow[(((size_t)b*2 + 1)*HH + h)*WW + w]  = a1;
}

// ============================================================================
// apply_offset + grid_sample fused.
// ============================================================================
__global__ __launch_bounds__(256) void warp_kernel(
    const float* __restrict__ f2, const float* __restrict__ flow,
    float* __restrict__ out)
{
    int idx = blockIdx.x*256 + threadIdx.x;
    int w = idx % WW;
    int h = (idx / WW) % HH;
    int c = (idx / HW) % CC;
    int b = idx / (HW*CC);

    float fx = flow[((size_t)b*2*HH + h)*WW + w];
    float fy = flow[(((size_t)b*2 + 1)*HH + h)*WW + w];

    float xx = fminf(fmaxf((float)w + fx, 0.f), (float)(WW-1));
    float yy = fminf(fmaxf((float)h + fy, 0.f), (float)(HH-1));
    float x0f = floorf(xx), y0f = floorf(yy);
    float wx = xx - x0f,  wy = yy - y0f;
    int x0 = (int)x0f, y0 = (int)y0f;
    int x1 = min(x0 + 1, WW-1);
    int y1 = min(y0 + 1, HH-1);

    const float* p = f2 + ((size_t)(b*CC + c))*HW;
    float v00 = p[y0*WW + x0];
    float v01 = p[y0*WW + x1];
    float v10 = p[y1*WW + x0];
    float v11 = p[y1*WW + x1];

    out[idx] = v00*(1.f-wx)*(1.f-wy) + v01*wx*(1.f-wy)
             + v10*(1.f-wx)*wy       + v11*wx*wy;
}

// ============================================================================
// launch
// ============================================================================
extern "C" void kernel_launch(void* const* d_in, const int* in_sizes, int n_in,
                              void* d_out, int out_size)
{
    const float* feat1 = (const float*)d_in[0];
    const float* feat2 = (const float*)d_in[1];
    const float* w1 = (const float*)d_in[2];
    const float* b1 = (const float*)d_in[3];
    const float* w2 = (const float*)d_in[4];
    const float* b2 = (const float*)d_in[5];
    const float* w3 = (const float*)d_in[6];
    const float* b3 = (const float*)d_in[7];
    const float* w4 = (const float*)d_in[8];
    const float* b4 = (const float*)d_in[9];
    float* out = (float*)d_out;

    float *p_corr, *p_h1, *p_h2, *p_h3, *p_flow;
    cudaGetSymbolAddress((void**)&p_corr, g_corr);
    cudaGetSymbolAddress((void**)&p_h1,   g_h1);
    cudaGetSymbolAddress((void**)&p_h2,   g_h2);
    cudaGetSymbolAddress((void**)&p_h3,   g_h3);
    cudaGetSymbolAddress((void**)&p_flow, g_flow);

    corr_kernel<<<dim3(HH/4, BB), 384>>>(feat1, feat2, p_corr);

    conv3x3_mma<49, 128, true><<<dim3(3, 32, BB*4), 128>>>(p_corr, w1, b1, p_h1);
    conv3x3_mma<128, 64, true><<<dim3(3, 32, BB*2), 128>>>(p_h1,  w2, b2, p_h2);
    conv3x3_mma<64,  32, true><<<dim3(3, 32, BB*1), 128>>>(p_h2,  w3, b3, p_h3);

    conv_last_kernel<<<(BB*HH*WW)/256, 256>>>(p_h3, w4, b4, p_flow);

    warp_kernel<<<(BB*CC*HH*WW)/256, 256>>>(feat2, p_flow, out);
}